// round 5
// baseline (speedup 1.0000x reference)
#include <cuda_runtime.h>
#include <cuda_fp16.h>
#include <cstdint>

#define N_TOK 8192
#define DIM   1024

// ---- fp16 mma tile config: CTA 128x256x32, warp 64x64, 8 warps ----
#define BM 128
#define BN 256
#define BK 32
#define NST 4
#define RSH 40                        // halves per smem row (80 B)
#define OPA (128 * 80)                // 10240 B  A per stage
#define OPB_ (256 * 80)               // 20480 B  B per stage
#define SS  (OPA + OPB_)              // 30720 B per stage
#define SMEM_BYTES (NST * SS)         // 122880 B

// ---- scratch (device globals; no allocation allowed) ----
__device__ __half g_X [N_TOK * DIM];
__device__ __half g_Q [N_TOK * DIM];
__device__ __half g_K [N_TOK * DIM];
__device__ __half g_V [N_TOK * DIM];
__device__ __half g_VT[N_TOK * DIM];
__device__ __half g_WT[3][DIM * DIM];
__device__ __half g_S [(size_t)N_TOK * N_TOK];
__device__ float  g_rinv[N_TOK];

// =================== helpers ===================
__device__ __forceinline__ uint32_t smem_u32(const void* p) {
    uint32_t a;
    asm("{ .reg .u64 t; cvta.to.shared.u64 t, %1; cvt.u32.u64 %0, t; }" : "=r"(a) : "l"(p));
    return a;
}
__device__ __forceinline__ void cp16(uint32_t dst, const void* src) {
    asm volatile("cp.async.cg.shared.global [%0], [%1], 16;" :: "r"(dst), "l"(src));
}
__device__ __forceinline__ void cp_commit() {
    asm volatile("cp.async.commit_group;" ::: "memory");
}
__device__ __forceinline__ void cp_wait2() {
    asm volatile("cp.async.wait_group 2;" ::: "memory");
}
__device__ __forceinline__ void ldsm4(uint32_t* r, uint32_t addr) {
    asm volatile("ldmatrix.sync.aligned.m8n8.x4.shared.b16 {%0,%1,%2,%3}, [%4];"
                 : "=r"(r[0]), "=r"(r[1]), "=r"(r[2]), "=r"(r[3]) : "r"(addr));
}
__device__ __forceinline__ void mma_f16(float* c, const uint32_t* a, uint32_t b0, uint32_t b1) {
    asm volatile(
        "mma.sync.aligned.m16n8k16.row.col.f32.f16.f16.f32 "
        "{%0,%1,%2,%3}, {%4,%5,%6,%7}, {%8,%9}, {%0,%1,%2,%3};"
        : "+f"(c[0]), "+f"(c[1]), "+f"(c[2]), "+f"(c[3])
        : "r"(a[0]), "r"(a[1]), "r"(a[2]), "r"(a[3]), "r"(b0), "r"(b1));
}

// =================== fp16 mma.sync GEMM (128x256 CTA, 64x64 warp) ===================
// acc = A[M,K] @ B[N,K]^T
// MODE 0: C fp32 = acc * alpha * row_scale[r]      (PV; final output)
// MODE 1: C fp16 = acc                             (projections)
// MODE 2: C fp16 = exp(alpha * acc)                (scores -> probabilities)
template<int MODE>
__global__ __launch_bounds__(256, 1)
void gemm_h(const __half* __restrict__ A, const __half* __restrict__ B,
            void* __restrict__ Cv, int M, int N, int K,
            float alpha, const float* __restrict__ row_scale)
{
    extern __shared__ char smraw[];
    const uint32_t sbase = smem_u32(smraw);
    const int tid  = threadIdx.x;
    const int wid  = tid >> 5, lane = tid & 31;
    const int wm   = wid & 1, wn = wid >> 1;          // 2 x 4 warp grid
    const int rowBase = blockIdx.y * BM;
    const int colBase = blockIdx.x * BN;
    const int nk = K / BK;

    // ---- gmem -> smem mapping: rows of 64B (32 halves), 16B chunks ----
    const int gr = tid >> 2;                 // 0..63
    const int seg = (tid & 3);
    const __half* gA = A + (size_t)(rowBase + gr) * K + seg * 8;
    const __half* gB = B + (size_t)(colBase + gr) * K + seg * 8;
    const size_t hop = (size_t)64 * K;
    const uint32_t dA = (uint32_t)gr * 80 + seg * 16;
    const uint32_t dB = OPA + dA;

    // ---- ldmatrix offsets ----
    const int quad = lane >> 3, lr = lane & 7;
    uint32_t aOff[4], bOff[4];
    #pragma unroll
    for (int mt = 0; mt < 4; mt++) {
        int r = wm * 64 + mt * 16 + (quad & 1) * 8 + lr;
        aOff[mt] = (uint32_t)(r * RSH + (quad >> 1) * 8) * 2;
    }
    #pragma unroll
    for (int p = 0; p < 4; p++) {
        int r = wn * 64 + p * 16 + (quad & 1) * 8 + lr;
        bOff[p] = OPA + (uint32_t)(r * RSH + (quad >> 1) * 8) * 2;
    }

    float acc[4][8][4];
    #pragma unroll
    for (int i = 0; i < 4; i++)
        #pragma unroll
        for (int j = 0; j < 8; j++)
            #pragma unroll
            for (int e = 0; e < 4; e++) acc[i][j][e] = 0.f;

    // ---- prologue: fill NST-1 stages (6 cp16 per thread per stage) ----
    #pragma unroll
    for (int s = 0; s < NST - 1; s++) {
        const uint32_t d = sbase + s * SS;
        const int k0 = s * BK;
        cp16(d + dA,           gA + k0);
        cp16(d + dA + 64 * 80, gA + hop + k0);
        #pragma unroll
        for (int h = 0; h < 4; h++)
            cp16(d + dB + h * 64 * 80, gB + h * hop + k0);
        cp_commit();
    }

    // ---- main loop ----
    for (int it = 0; it < nk; it++) {
        cp_wait2();
        __syncthreads();

        if (it + NST - 1 < nk) {
            const uint32_t d = sbase + ((it + NST - 1) & (NST - 1)) * SS;
            const int k0 = (it + NST - 1) * BK;
            cp16(d + dA,           gA + k0);
            cp16(d + dA + 64 * 80, gA + hop + k0);
            #pragma unroll
            for (int h = 0; h < 4; h++)
                cp16(d + dB + h * 64 * 80, gB + h * hop + k0);
        }
        cp_commit();

        const uint32_t st = sbase + (it & (NST - 1)) * SS;
        #pragma unroll
        for (int kk = 0; kk < 2; kk++) {
            const uint32_t ko = kk * 32;     // 16 halves = 32 B
            uint32_t a[4][4], b[4][4];
            #pragma unroll
            for (int mt = 0; mt < 4; mt++) ldsm4(a[mt], st + aOff[mt] + ko);
            #pragma unroll
            for (int p = 0; p < 4; p++)    ldsm4(b[p],  st + bOff[p] + ko);
            #pragma unroll
            for (int mt = 0; mt < 4; mt++)
                #pragma unroll
                for (int p = 0; p < 4; p++) {
                    mma_f16(acc[mt][2*p],   a[mt], b[p][0], b[p][2]);
                    mma_f16(acc[mt][2*p+1], a[mt], b[p][1], b[p][3]);
                }
        }
        __syncthreads();
    }

    // ---- epilogue ----
    const int g = lane >> 2, tg = lane & 3;
    #pragma unroll
    for (int mt = 0; mt < 4; mt++) {
        const int r0 = rowBase + wm * 64 + mt * 16 + g;
        float sc0 = 1.f, sc1 = 1.f;
        if (MODE == 0) {
            sc0 = alpha * row_scale[r0];
            sc1 = alpha * row_scale[r0 + 8];
        }
        #pragma unroll
        for (int nt = 0; nt < 8; nt++) {
            const int c = colBase + wn * 64 + nt * 8 + tg * 2;
            float v0 = acc[mt][nt][0], v1 = acc[mt][nt][1];
            float v2 = acc[mt][nt][2], v3 = acc[mt][nt][3];
            if (MODE == 0) {
                float* C = (float*)Cv;
                *(float2*)&C[(size_t)r0 * N + c]       = make_float2(v0 * sc0, v1 * sc0);
                *(float2*)&C[(size_t)(r0 + 8) * N + c] = make_float2(v2 * sc1, v3 * sc1);
            } else {
                if (MODE == 2) {
                    v0 = __expf(alpha * v0); v1 = __expf(alpha * v1);
                    v2 = __expf(alpha * v2); v3 = __expf(alpha * v3);
                }
                __half* C = (__half*)Cv;
                *(__half2*)&C[(size_t)r0 * N + c]       = __floats2half2_rn(v0, v1);
                *(__half2*)&C[(size_t)(r0 + 8) * N + c] = __floats2half2_rn(v2, v3);
            }
        }
    }
}

// =================== transposes ===================
__global__ void transpose_f2h(const float* __restrict__ in, __half* __restrict__ out, int R, int C)
{
    __shared__ float t[32][33];
    const int c0 = blockIdx.x * 32, r0 = blockIdx.y * 32;
    const int x = threadIdx.x, y = threadIdx.y;
    #pragma unroll
    for (int j = 0; j < 32; j += 8)
        t[y + j][x] = in[(size_t)(r0 + y + j) * C + c0 + x];
    __syncthreads();
    #pragma unroll
    for (int j = 0; j < 32; j += 8)
        out[(size_t)(c0 + y + j) * R + r0 + x] = __float2half_rn(t[x][y + j]);
}
__global__ void transpose_h2h(const __half* __restrict__ in, __half* __restrict__ out, int R, int C)
{
    __shared__ __half t[32][34];
    const int c0 = blockIdx.x * 32, r0 = blockIdx.y * 32;
    const int x = threadIdx.x, y = threadIdx.y;
    #pragma unroll
    for (int j = 0; j < 32; j += 8)
        t[y + j][x] = in[(size_t)(r0 + y + j) * C + c0 + x];
    __syncthreads();
    #pragma unroll
    for (int j = 0; j < 32; j += 8)
        out[(size_t)(c0 + y + j) * R + r0 + x] = t[x][y + j];
}

// =================== round x -> fp16 ===================
__global__ __launch_bounds__(256)
void round_h(const float* __restrict__ in, __half* __restrict__ out, int n4)
{
    int i = blockIdx.x * 256 + threadIdx.x;
    if (i < n4) {
        float4 v = ((const float4*)in)[i];
        __half2* o = (__half2*)(out + (size_t)i * 4);
        o[0] = __floats2half2_rn(v.x, v.y);
        o[1] = __floats2half2_rn(v.z, v.w);
    }
}

// =================== row sums of fp16 P -> 1/sum (fp32) ===================
__global__ __launch_bounds__(256)
void rowsum_inv(const __half* __restrict__ P, float* __restrict__ rinv)
{
    const int tid = threadIdx.x;
    const uint4* p = (const uint4*)(P + (size_t)blockIdx.x * N_TOK);
    float s = 0.f;
    for (int i = tid; i < N_TOK / 8; i += 256) {
        uint4 u = p[i];
        float2 a = __half22float2(*(__half2*)&u.x);
        float2 b = __half22float2(*(__half2*)&u.y);
        float2 c = __half22float2(*(__half2*)&u.z);
        float2 d = __half22float2(*(__half2*)&u.w);
        s += (a.x + a.y) + (b.x + b.y) + (c.x + c.y) + (d.x + d.y);
    }
    #pragma unroll
    for (int o = 16; o; o >>= 1) s += __shfl_xor_sync(0xffffffffu, s, o);
    __shared__ float sh[8];
    if ((tid & 31) == 0) sh[tid >> 5] = s;
    __syncthreads();
    if (tid == 0) {
        float t = 0.f;
        #pragma unroll
        for (int w = 0; w < 8; w++) t += sh[w];
        rinv[blockIdx.x] = 1.0f / t;
    }
}

// =================== host ===================
extern "C" void kernel_launch(void* const* d_in, const int* in_sizes, int n_in,
                              void* d_out, int out_size)
{
    const float* x  = (const float*)d_in[0];
    const float* Wq = (const float*)d_in[1];
    const float* Wk = (const float*)d_in[2];
    const float* Wv = (const float*)d_in[3];
    float* out = (float*)d_out;

    __half *X, *Q, *K, *V, *VT, *WT, *S;
    float *Rinv;
    cudaGetSymbolAddress((void**)&X,    g_X);
    cudaGetSymbolAddress((void**)&Q,    g_Q);
    cudaGetSymbolAddress((void**)&K,    g_K);
    cudaGetSymbolAddress((void**)&V,    g_V);
    cudaGetSymbolAddress((void**)&VT,   g_VT);
    cudaGetSymbolAddress((void**)&WT,   g_WT);
    cudaGetSymbolAddress((void**)&S,    g_S);
    cudaGetSymbolAddress((void**)&Rinv, g_rinv);
    __half* WkT = WT;
    __half* WqT = WT + (size_t)DIM * DIM;
    __half* WvT = WT + (size_t)2 * DIM * DIM;

    cudaFuncSetAttribute(gemm_h<0>, cudaFuncAttributeMaxDynamicSharedMemorySize, SMEM_BYTES);
    cudaFuncSetAttribute(gemm_h<1>, cudaFuncAttributeMaxDynamicSharedMemorySize, SMEM_BYTES);
    cudaFuncSetAttribute(gemm_h<2>, cudaFuncAttributeMaxDynamicSharedMemorySize, SMEM_BYTES);

    const dim3 tblk(32, 8);

    // prep: x -> fp16; W -> fp16 transposed ([in,out] -> [out,in])
    round_h<<<(N_TOK * DIM / 4 + 255) / 256, 256>>>(x, X, N_TOK * DIM / 4);
    transpose_f2h<<<dim3(32, 32), tblk>>>(Wk, WkT, DIM, DIM);
    transpose_f2h<<<dim3(32, 32), tblk>>>(Wq, WqT, DIM, DIM);
    transpose_f2h<<<dim3(32, 32), tblk>>>(Wv, WvT, DIM, DIM);

    const dim3 gProj(DIM / BN, N_TOK / BM);     // (4, 64)
    const dim3 gScore(N_TOK / BN, N_TOK / BM);  // (32, 64)

    // reference name-swap: q = x@Wk, k = x@Wq, v = x@Wv
    gemm_h<1><<<gProj, 256, SMEM_BYTES>>>(X, WkT, Q, N_TOK, DIM, DIM, 1.f, nullptr);
    gemm_h<1><<<gProj, 256, SMEM_BYTES>>>(X, WqT, K, N_TOK, DIM, DIM, 1.f, nullptr);
    gemm_h<1><<<gProj, 256, SMEM_BYTES>>>(X, WvT, V, N_TOK, DIM, DIM, 1.f, nullptr);

    // V^T for PV GEMM B operand
    transpose_h2h<<<dim3(DIM / 32, N_TOK / 32), tblk>>>(V, VT, N_TOK, DIM);

    // P = exp(QK^T / 32) fused in epilogue, stored fp16
    gemm_h<2><<<gScore, 256, SMEM_BYTES>>>(Q, K, S, N_TOK, N_TOK, DIM, 0.03125f, nullptr);

    // rinv = 1 / rowsum(P)
    rowsum_inv<<<N_TOK, 256>>>(S, Rinv);

    // out = diag(rinv) * P @ V
    gemm_h<0><<<gProj, 256, SMEM_BYTES>>>(S, VT, out, N_TOK, DIM, N_TOK, 1.f, Rinv);
}

// round 6
// speedup vs baseline: 1.0975x; 1.0975x over previous
#include <cuda_runtime.h>
#include <cuda_fp16.h>
#include <cstdint>

#define N_TOK 8192
#define DIM   1024

// ---- fp16 mma tile config: CTA 128x128x32, warp 64x32, 8 warps, 2 CTA/SM ----
#define BM 128
#define BN 128
#define BK 32
#define NST 5
#define RSH 40                        // halves per smem row (80 B, conflict-free ldmatrix)
#define OPB (128 * RSH * 2)           // 10240 B per operand per stage
#define SS  (2 * OPB)                 // 20480 B per stage
#define SMEM_BYTES (NST * SS)         // 102400 B

// ---- scratch (device globals; no allocation allowed) ----
__device__ __half g_X [N_TOK * DIM];
__device__ __half g_Q [N_TOK * DIM];
__device__ __half g_K [N_TOK * DIM];
__device__ __half g_V [N_TOK * DIM];
__device__ __half g_VT[N_TOK * DIM];
__device__ __half g_WT[3][DIM * DIM];
__device__ __half g_S [(size_t)N_TOK * N_TOK];
__device__ float  g_rinv[N_TOK];

// =================== helpers ===================
__device__ __forceinline__ uint32_t smem_u32(const void* p) {
    uint32_t a;
    asm("{ .reg .u64 t; cvta.to.shared.u64 t, %1; cvt.u32.u64 %0, t; }" : "=r"(a) : "l"(p));
    return a;
}
__device__ __forceinline__ void cp16(uint32_t dst, const void* src) {
    asm volatile("cp.async.cg.shared.global [%0], [%1], 16;" :: "r"(dst), "l"(src));
}
__device__ __forceinline__ void cp_commit() {
    asm volatile("cp.async.commit_group;" ::: "memory");
}
__device__ __forceinline__ void cp_wait3() {
    asm volatile("cp.async.wait_group 3;" ::: "memory");
}
__device__ __forceinline__ void ldsm4(uint32_t* r, uint32_t addr) {
    asm volatile("ldmatrix.sync.aligned.m8n8.x4.shared.b16 {%0,%1,%2,%3}, [%4];"
                 : "=r"(r[0]), "=r"(r[1]), "=r"(r[2]), "=r"(r[3]) : "r"(addr));
}
__device__ __forceinline__ void mma_f16(float* c, const uint32_t* a, uint32_t b0, uint32_t b1) {
    asm volatile(
        "mma.sync.aligned.m16n8k16.row.col.f32.f16.f16.f32 "
        "{%0,%1,%2,%3}, {%4,%5,%6,%7}, {%8,%9}, {%0,%1,%2,%3};"
        : "+f"(c[0]), "+f"(c[1]), "+f"(c[2]), "+f"(c[3])
        : "r"(a[0]), "r"(a[1]), "r"(a[2]), "r"(a[3]), "r"(b0), "r"(b1));
}

// =================== fp16 mma.sync GEMM ===================
// acc = A[M,K] @ B[N,K]^T   (A,B fp16; acc fp32)
// MODE 0: C fp32 = acc * alpha * row_scale[r]      (PV; final output)
// MODE 1: C fp16 = acc                             (projections)
// MODE 2: C fp16 = exp(alpha * acc)                (scores -> probabilities)
template<int MODE>
__global__ __launch_bounds__(256, 2)
void gemm_h(const __half* __restrict__ A, const __half* __restrict__ B,
            void* __restrict__ Cv, int M, int N, int K,
            float alpha, const float* __restrict__ row_scale)
{
    extern __shared__ char smraw[];
    const uint32_t sbase = smem_u32(smraw);
    const int tid  = threadIdx.x;
    const int wid  = tid >> 5, lane = tid & 31;
    const int wm   = wid & 1, wn = wid >> 1;
    const int rowBase = blockIdx.y * BM;
    const int colBase = blockIdx.x * BN;
    const int nk = K / BK;

    // ---- gmem -> smem: rows of 64B (32 halves); 2 x 16B per operand per thread ----
    const int gr = tid >> 2;                 // 0..63
    const int seg = tid & 3;
    const __half* gA = A + (size_t)(rowBase + gr) * K + seg * 8;
    const __half* gB = B + (size_t)(colBase + gr) * K + seg * 8;
    const size_t hop = (size_t)64 * K;
    const uint32_t dA = (uint32_t)gr * 80 + seg * 16;
    const uint32_t dB = OPB + dA;

    // ---- ldmatrix offsets ----
    const int quad = lane >> 3, lr = lane & 7;
    uint32_t aOff[4], bOff[2];
    #pragma unroll
    for (int mt = 0; mt < 4; mt++) {
        int r = wm * 64 + mt * 16 + (quad & 1) * 8 + lr;
        aOff[mt] = (uint32_t)(r * RSH + (quad >> 1) * 8) * 2;
    }
    #pragma unroll
    for (int p = 0; p < 2; p++) {
        int r = wn * 32 + p * 16 + (quad & 1) * 8 + lr;
        bOff[p] = OPB + (uint32_t)(r * RSH + (quad >> 1) * 8) * 2;
    }

    float acc[4][4][4];
    #pragma unroll
    for (int i = 0; i < 4; i++)
        #pragma unroll
        for (int j = 0; j < 4; j++)
            #pragma unroll
            for (int e = 0; e < 4; e++) acc[i][j][e] = 0.f;

    // ---- prologue: fill NST-1 stages ----
    #pragma unroll
    for (int s = 0; s < NST - 1; s++) {
        const uint32_t d = sbase + s * SS;
        const int k0 = s * BK;
        cp16(d + dA,           gA + k0);
        cp16(d + dA + 64 * 80, gA + hop + k0);
        cp16(d + dB,           gB + k0);
        cp16(d + dB + 64 * 80, gB + hop + k0);
        cp_commit();
    }

    // ---- main loop: ONE barrier per iteration ----
    int sRead = 0, sWrite = NST - 1;
    for (int it = 0; it < nk; it++) {
        cp_wait3();
        __syncthreads();

        if (it + NST - 1 < nk) {
            const uint32_t d = sbase + sWrite * SS;
            const int k0 = (it + NST - 1) * BK;
            cp16(d + dA,           gA + k0);
            cp16(d + dA + 64 * 80, gA + hop + k0);
            cp16(d + dB,           gB + k0);
            cp16(d + dB + 64 * 80, gB + hop + k0);
        }
        cp_commit();
        if (++sWrite == NST) sWrite = 0;

        const uint32_t st = sbase + sRead * SS;
        if (++sRead == NST) sRead = 0;
        #pragma unroll
        for (int kk = 0; kk < 2; kk++) {
            const uint32_t ko = kk * 32;     // 16 halves = 32 B
            uint32_t a[4][4], b[2][4];
            #pragma unroll
            for (int mt = 0; mt < 4; mt++) ldsm4(a[mt], st + aOff[mt] + ko);
            #pragma unroll
            for (int p = 0; p < 2; p++)    ldsm4(b[p],  st + bOff[p] + ko);
            #pragma unroll
            for (int mt = 0; mt < 4; mt++)
                #pragma unroll
                for (int p = 0; p < 2; p++) {
                    mma_f16(acc[mt][2*p],   a[mt], b[p][0], b[p][2]);
                    mma_f16(acc[mt][2*p+1], a[mt], b[p][1], b[p][3]);
                }
        }
        // no trailing barrier: stage overwritten at iter it+1 is (it)%NST's
        // predecessor, whose readers all passed the top-of-iter barrier.
    }

    // ---- epilogue ----
    const int g = lane >> 2, tg = lane & 3;
    #pragma unroll
    for (int mt = 0; mt < 4; mt++) {
        const int r0 = rowBase + wm * 64 + mt * 16 + g;
        float sc0 = 1.f, sc1 = 1.f;
        if (MODE == 0) {
            sc0 = alpha * row_scale[r0];
            sc1 = alpha * row_scale[r0 + 8];
        }
        #pragma unroll
        for (int nt = 0; nt < 4; nt++) {
            const int c = colBase + wn * 32 + nt * 8 + tg * 2;
            float v0 = acc[mt][nt][0], v1 = acc[mt][nt][1];
            float v2 = acc[mt][nt][2], v3 = acc[mt][nt][3];
            if (MODE == 0) {
                float* C = (float*)Cv;
                *(float2*)&C[(size_t)r0 * N + c]       = make_float2(v0 * sc0, v1 * sc0);
                *(float2*)&C[(size_t)(r0 + 8) * N + c] = make_float2(v2 * sc1, v3 * sc1);
            } else {
                if (MODE == 2) {
                    v0 = __expf(alpha * v0); v1 = __expf(alpha * v1);
                    v2 = __expf(alpha * v2); v3 = __expf(alpha * v3);
                }
                __half* C = (__half*)Cv;
                *(__half2*)&C[(size_t)r0 * N + c]       = __floats2half2_rn(v0, v1);
                *(__half2*)&C[(size_t)(r0 + 8) * N + c] = __floats2half2_rn(v2, v3);
            }
        }
    }
}

// =================== transposes ===================
__global__ void transpose_f2h(const float* __restrict__ in, __half* __restrict__ out, int R, int C)
{
    __shared__ float t[32][33];
    const int c0 = blockIdx.x * 32, r0 = blockIdx.y * 32;
    const int x = threadIdx.x, y = threadIdx.y;
    #pragma unroll
    for (int j = 0; j < 32; j += 8)
        t[y + j][x] = in[(size_t)(r0 + y + j) * C + c0 + x];
    __syncthreads();
    #pragma unroll
    for (int j = 0; j < 32; j += 8)
        out[(size_t)(c0 + y + j) * R + r0 + x] = __float2half_rn(t[x][y + j]);
}
__global__ void transpose_h2h(const __half* __restrict__ in, __half* __restrict__ out, int R, int C)
{
    __shared__ __half t[32][34];
    const int c0 = blockIdx.x * 32, r0 = blockIdx.y * 32;
    const int x = threadIdx.x, y = threadIdx.y;
    #pragma unroll
    for (int j = 0; j < 32; j += 8)
        t[y + j][x] = in[(size_t)(r0 + y + j) * C + c0 + x];
    __syncthreads();
    #pragma unroll
    for (int j = 0; j < 32; j += 8)
        out[(size_t)(c0 + y + j) * R + r0 + x] = t[x][y + j];
}

// =================== round x -> fp16 ===================
__global__ __launch_bounds__(256)
void round_h(const float* __restrict__ in, __half* __restrict__ out, int n4)
{
    int i = blockIdx.x * 256 + threadIdx.x;
    if (i < n4) {
        float4 v = ((const float4*)in)[i];
        __half2* o = (__half2*)(out + (size_t)i * 4);
        o[0] = __floats2half2_rn(v.x, v.y);
        o[1] = __floats2half2_rn(v.z, v.w);
    }
}

// =================== row sums of fp16 P -> 1/sum (fp32) ===================
__global__ __launch_bounds__(256)
void rowsum_inv(const __half* __restrict__ P, float* __restrict__ rinv)
{
    const int tid = threadIdx.x;
    const uint4* p = (const uint4*)(P + (size_t)blockIdx.x * N_TOK);
    float s = 0.f;
    for (int i = tid; i < N_TOK / 8; i += 256) {
        uint4 u = p[i];
        float2 a = __half22float2(*(__half2*)&u.x);
        float2 b = __half22float2(*(__half2*)&u.y);
        float2 c = __half22float2(*(__half2*)&u.z);
        float2 d = __half22float2(*(__half2*)&u.w);
        s += (a.x + a.y) + (b.x + b.y) + (c.x + c.y) + (d.x + d.y);
    }
    #pragma unroll
    for (int o = 16; o; o >>= 1) s += __shfl_xor_sync(0xffffffffu, s, o);
    __shared__ float sh[8];
    if ((tid & 31) == 0) sh[tid >> 5] = s;
    __syncthreads();
    if (tid == 0) {
        float t = 0.f;
        #pragma unroll
        for (int w = 0; w < 8; w++) t += sh[w];
        rinv[blockIdx.x] = 1.0f / t;
    }
}

// =================== host ===================
extern "C" void kernel_launch(void* const* d_in, const int* in_sizes, int n_in,
                              void* d_out, int out_size)
{
    const float* x  = (const float*)d_in[0];
    const float* Wq = (const float*)d_in[1];
    const float* Wk = (const float*)d_in[2];
    const float* Wv = (const float*)d_in[3];
    float* out = (float*)d_out;

    __half *X, *Q, *K, *V, *VT, *WT, *S;
    float *Rinv;
    cudaGetSymbolAddress((void**)&X,    g_X);
    cudaGetSymbolAddress((void**)&Q,    g_Q);
    cudaGetSymbolAddress((void**)&K,    g_K);
    cudaGetSymbolAddress((void**)&V,    g_V);
    cudaGetSymbolAddress((void**)&VT,   g_VT);
    cudaGetSymbolAddress((void**)&WT,   g_WT);
    cudaGetSymbolAddress((void**)&S,    g_S);
    cudaGetSymbolAddress((void**)&Rinv, g_rinv);
    __half* WkT = WT;
    __half* WqT = WT + (size_t)DIM * DIM;
    __half* WvT = WT + (size_t)2 * DIM * DIM;

    cudaFuncSetAttribute(gemm_h<0>, cudaFuncAttributeMaxDynamicSharedMemorySize, SMEM_BYTES);
    cudaFuncSetAttribute(gemm_h<1>, cudaFuncAttributeMaxDynamicSharedMemorySize, SMEM_BYTES);
    cudaFuncSetAttribute(gemm_h<2>, cudaFuncAttributeMaxDynamicSharedMemorySize, SMEM_BYTES);

    const dim3 tblk(32, 8);

    // prep: x -> fp16; W -> fp16 transposed ([in,out] -> [out,in])
    round_h<<<(N_TOK * DIM / 4 + 255) / 256, 256>>>(x, X, N_TOK * DIM / 4);
    transpose_f2h<<<dim3(32, 32), tblk>>>(Wk, WkT, DIM, DIM);
    transpose_f2h<<<dim3(32, 32), tblk>>>(Wq, WqT, DIM, DIM);
    transpose_f2h<<<dim3(32, 32), tblk>>>(Wv, WvT, DIM, DIM);

    const dim3 gProj(DIM / BN, N_TOK / BM);     // (8, 64)
    const dim3 gScore(N_TOK / BN, N_TOK / BM);  // (64, 64)

    // reference name-swap: q = x@Wk, k = x@Wq, v = x@Wv
    gemm_h<1><<<gProj, 256, SMEM_BYTES>>>(X, WkT, Q, N_TOK, DIM, DIM, 1.f, nullptr);
    gemm_h<1><<<gProj, 256, SMEM_BYTES>>>(X, WqT, K, N_TOK, DIM, DIM, 1.f, nullptr);
    gemm_h<1><<<gProj, 256, SMEM_BYTES>>>(X, WvT, V, N_TOK, DIM, DIM, 1.f, nullptr);

    // V^T for PV GEMM B operand
    transpose_h2h<<<dim3(DIM / 32, N_TOK / 32), tblk>>>(V, VT, N_TOK, DIM);

    // P = exp(QK^T / 32) fused in epilogue, stored fp16
    gemm_h<2><<<gScore, 256, SMEM_BYTES>>>(Q, K, S, N_TOK, N_TOK, DIM, 0.03125f, nullptr);

    // rinv = 1 / rowsum(P)
    rowsum_inv<<<N_TOK, 256>>>(S, Rinv);

    // out = diag(rinv) * P @ V
    gemm_h<0><<<gProj, 256, SMEM_BYTES>>>(S, VT, out, N_TOK, DIM, N_TOK, 1.f, Rinv);
}

// round 7
// speedup vs baseline: 1.1676x; 1.0640x over previous
#include <cuda_runtime.h>
#include <cuda_fp16.h>
#include <cstdint>

#define N_TOK 8192
#define DIM   1024

// ---- fp16 mma tile config: CTA 128x128x32, warp 64x32, 8 warps, 2 CTA/SM ----
#define BM 128
#define BN 128
#define BK 32
#define NST 4
#define RSH 40                        // halves per smem row (80 B)
#define OPB (128 * RSH * 2)           // 10240 B per operand per stage
#define SS  (2 * OPB)                 // 20480 B per stage
#define SMEM_BYTES (NST * SS)         // 81920 B

// ---- scratch (device globals; no allocation allowed) ----
__device__ __half g_X [N_TOK * DIM];
__device__ __half g_Q [N_TOK * DIM];
__device__ __half g_K [N_TOK * DIM];
__device__ __half g_VT[N_TOK * DIM];
__device__ __half g_WT[3][DIM * DIM];
__device__ __half g_S [(size_t)N_TOK * N_TOK];
__device__ float  g_spart[(size_t)64 * N_TOK];          // score row partial sums
__device__ float  g_opart[(size_t)4 * N_TOK * DIM];     // PV split-K partials
__device__ float  g_rinv[N_TOK];

// =================== helpers ===================
__device__ __forceinline__ uint32_t smem_u32(const void* p) {
    uint32_t a;
    asm("{ .reg .u64 t; cvta.to.shared.u64 t, %1; cvt.u32.u64 %0, t; }" : "=r"(a) : "l"(p));
    return a;
}
__device__ __forceinline__ void cp16(uint32_t dst, const void* src) {
    asm volatile("cp.async.cg.shared.global [%0], [%1], 16;" :: "r"(dst), "l"(src));
}
__device__ __forceinline__ void cp_commit() {
    asm volatile("cp.async.commit_group;" ::: "memory");
}
__device__ __forceinline__ void cp_wait2() {
    asm volatile("cp.async.wait_group 2;" ::: "memory");
}
__device__ __forceinline__ void ldsm4(uint32_t* r, uint32_t addr) {
    asm volatile("ldmatrix.sync.aligned.m8n8.x4.shared.b16 {%0,%1,%2,%3}, [%4];"
                 : "=r"(r[0]), "=r"(r[1]), "=r"(r[2]), "=r"(r[3]) : "r"(addr));
}
__device__ __forceinline__ void mma_f16(float* c, const uint32_t* a, uint32_t b0, uint32_t b1) {
    asm volatile(
        "mma.sync.aligned.m16n8k16.row.col.f32.f16.f16.f32 "
        "{%0,%1,%2,%3}, {%4,%5,%6,%7}, {%8,%9}, {%0,%1,%2,%3};"
        : "+f"(c[0]), "+f"(c[1]), "+f"(c[2]), "+f"(c[3])
        : "r"(a[0]), "r"(a[1]), "r"(a[2]), "r"(a[3]), "r"(b0), "r"(b1));
}

// =================== fp16 mma.sync GEMM ===================
// acc = A[M,K_slice] @ B[N,K_slice]^T  (K sliced by gridDim.z)
// MODE 1: C fp16 = acc                          (Q,K projections)
// MODE 2: C fp16 = exp(alpha*acc); row partial sums of exp -> spart
// MODE 3: C^T fp16 = acc  (writes VT via smem transpose)
// MODE 4: partial[z] fp32 = acc                 (PV split-K)
template<int MODE>
__global__ __launch_bounds__(256, 2)
void gemm_h(const __half* __restrict__ A, const __half* __restrict__ B,
            void* __restrict__ Cv, int M, int N, int K,
            float alpha, float* __restrict__ spart)
{
    extern __shared__ char smraw[];
    const uint32_t sbase = smem_u32(smraw);
    const int tid  = threadIdx.x;
    const int wid  = tid >> 5, lane = tid & 31;
    const int wm   = wid & 1, wn = wid >> 1;
    const int rowBase = blockIdx.y * BM;
    const int colBase = blockIdx.x * BN;
    const int kPer = K / gridDim.z;
    const int kOff = blockIdx.z * kPer;
    const int nk = kPer / BK;

    // ---- gmem -> smem: rows of 64B (32 halves); 2 x 16B per operand per thread ----
    const int gr = tid >> 2;                 // 0..63
    const int seg = tid & 3;
    const __half* gA = A + (size_t)(rowBase + gr) * K + kOff + seg * 8;
    const __half* gB = B + (size_t)(colBase + gr) * K + kOff + seg * 8;
    const size_t hop = (size_t)64 * K;
    const uint32_t dA = (uint32_t)gr * 80 + seg * 16;
    const uint32_t dB = OPB + dA;

    // ---- ldmatrix offsets ----
    const int quad = lane >> 3, lr = lane & 7;
    uint32_t aOff[4], bOff[2];
    #pragma unroll
    for (int mt = 0; mt < 4; mt++) {
        int r = wm * 64 + mt * 16 + (quad & 1) * 8 + lr;
        aOff[mt] = (uint32_t)(r * RSH + (quad >> 1) * 8) * 2;
    }
    #pragma unroll
    for (int p = 0; p < 2; p++) {
        int r = wn * 32 + p * 16 + (quad & 1) * 8 + lr;
        bOff[p] = OPB + (uint32_t)(r * RSH + (quad >> 1) * 8) * 2;
    }

    float acc[4][4][4];
    #pragma unroll
    for (int i = 0; i < 4; i++)
        #pragma unroll
        for (int j = 0; j < 4; j++)
            #pragma unroll
            for (int e = 0; e < 4; e++) acc[i][j][e] = 0.f;

    // ---- prologue ----
    #pragma unroll
    for (int s = 0; s < NST - 1; s++) {
        const uint32_t d = sbase + s * SS;
        const int k0 = s * BK;
        cp16(d + dA,           gA + k0);
        cp16(d + dA + 64 * 80, gA + hop + k0);
        cp16(d + dB,           gB + k0);
        cp16(d + dB + 64 * 80, gB + hop + k0);
        cp_commit();
    }

    // ---- main loop ----
    for (int it = 0; it < nk; it++) {
        cp_wait2();
        __syncthreads();

        if (it + NST - 1 < nk) {
            const uint32_t d = sbase + ((it + NST - 1) & (NST - 1)) * SS;
            const int k0 = (it + NST - 1) * BK;
            cp16(d + dA,           gA + k0);
            cp16(d + dA + 64 * 80, gA + hop + k0);
            cp16(d + dB,           gB + k0);
            cp16(d + dB + 64 * 80, gB + hop + k0);
        }
        cp_commit();

        const uint32_t st = sbase + (it & (NST - 1)) * SS;
        #pragma unroll
        for (int kk = 0; kk < 2; kk++) {
            const uint32_t ko = kk * 32;
            uint32_t a[4][4], b[2][4];
            #pragma unroll
            for (int mt = 0; mt < 4; mt++) ldsm4(a[mt], st + aOff[mt] + ko);
            #pragma unroll
            for (int p = 0; p < 2; p++)    ldsm4(b[p],  st + bOff[p] + ko);
            #pragma unroll
            for (int mt = 0; mt < 4; mt++)
                #pragma unroll
                for (int p = 0; p < 2; p++) {
                    mma_f16(acc[mt][2*p],   a[mt], b[p][0], b[p][2]);
                    mma_f16(acc[mt][2*p+1], a[mt], b[p][1], b[p][3]);
                }
        }
        __syncthreads();
    }

    // ---- epilogue ----
    const int g = lane >> 2, tg = lane & 3;

    if (MODE == 1 || MODE == 2) {
        float rs0[4] = {0.f, 0.f, 0.f, 0.f};
        float rs1[4] = {0.f, 0.f, 0.f, 0.f};
        __half* C = (__half*)Cv;
        #pragma unroll
        for (int mt = 0; mt < 4; mt++) {
            const int r0 = rowBase + wm * 64 + mt * 16 + g;
            #pragma unroll
            for (int nt = 0; nt < 4; nt++) {
                const int c = colBase + wn * 32 + nt * 8 + tg * 2;
                float v0 = acc[mt][nt][0], v1 = acc[mt][nt][1];
                float v2 = acc[mt][nt][2], v3 = acc[mt][nt][3];
                if (MODE == 2) {
                    v0 = __expf(alpha * v0); v1 = __expf(alpha * v1);
                    v2 = __expf(alpha * v2); v3 = __expf(alpha * v3);
                    rs0[mt] += v0 + v1;
                    rs1[mt] += v2 + v3;
                }
                *(__half2*)&C[(size_t)r0 * N + c]       = __floats2half2_rn(v0, v1);
                *(__half2*)&C[(size_t)(r0 + 8) * N + c] = __floats2half2_rn(v2, v3);
            }
        }
        if (MODE == 2) {
            // reduce row partials: over tg lanes, then across wn warps via smem
            float* part = (float*)smraw;           // [4][128]
            __syncthreads();                       // pipeline smem now dead
            #pragma unroll
            for (int mt = 0; mt < 4; mt++) {
                float a0 = rs0[mt], a1 = rs1[mt];
                a0 += __shfl_xor_sync(0xffffffffu, a0, 1);
                a0 += __shfl_xor_sync(0xffffffffu, a0, 2);
                a1 += __shfl_xor_sync(0xffffffffu, a1, 1);
                a1 += __shfl_xor_sync(0xffffffffu, a1, 2);
                if (tg == 0) {
                    part[wn * 128 + wm * 64 + mt * 16 + g]     = a0;
                    part[wn * 128 + wm * 64 + mt * 16 + g + 8] = a1;
                }
            }
            __syncthreads();
            if (tid < 128) {
                float s = part[tid] + part[128 + tid] + part[256 + tid] + part[384 + tid];
                spart[(size_t)blockIdx.x * M + rowBase + tid] = s;
            }
        }
    } else if (MODE == 3) {
        // transpose tile in smem, write VT coalesced
        __half* buf = (__half*)smraw;              // [128 cols][136 rows]
        __syncthreads();
        #pragma unroll
        for (int mt = 0; mt < 4; mt++) {
            const int r0 = wm * 64 + mt * 16 + g;
            #pragma unroll
            for (int nt = 0; nt < 4; nt++) {
                const int c = wn * 32 + nt * 8 + tg * 2;
                buf[(c    ) * 136 + r0    ] = __float2half_rn(acc[mt][nt][0]);
                buf[(c + 1) * 136 + r0    ] = __float2half_rn(acc[mt][nt][1]);
                buf[(c    ) * 136 + r0 + 8] = __float2half_rn(acc[mt][nt][2]);
                buf[(c + 1) * 136 + r0 + 8] = __float2half_rn(acc[mt][nt][3]);
            }
        }
        __syncthreads();
        __half* VT = (__half*)Cv;                  // [N][M] row stride M
        #pragma unroll
        for (int ch = tid; ch < 128 * 16; ch += 256) {
            const int cc = ch >> 4, sg = ch & 15;
            uint4 v = *(uint4*)&buf[cc * 136 + sg * 8];
            *(uint4*)&VT[(size_t)(colBase + cc) * M + rowBase + sg * 8] = v;
        }
    } else {  // MODE 4: fp32 split-K partial
        float* C = (float*)Cv + (size_t)blockIdx.z * M * N;
        #pragma unroll
        for (int mt = 0; mt < 4; mt++) {
            const int r0 = rowBase + wm * 64 + mt * 16 + g;
            #pragma unroll
            for (int nt = 0; nt < 4; nt++) {
                const int c = colBase + wn * 32 + nt * 8 + tg * 2;
                *(float2*)&C[(size_t)r0 * N + c]       = make_float2(acc[mt][nt][0], acc[mt][nt][1]);
                *(float2*)&C[(size_t)(r0 + 8) * N + c] = make_float2(acc[mt][nt][2], acc[mt][nt][3]);
            }
        }
    }
}

// =================== transpose fp32 -> fp16 (weights) ===================
__global__ void transpose_f2h(const float* __restrict__ in, __half* __restrict__ out, int R, int C)
{
    __shared__ float t[32][33];
    const int c0 = blockIdx.x * 32, r0 = blockIdx.y * 32;
    const int x = threadIdx.x, y = threadIdx.y;
    #pragma unroll
    for (int j = 0; j < 32; j += 8)
        t[y + j][x] = in[(size_t)(r0 + y + j) * C + c0 + x];
    __syncthreads();
    #pragma unroll
    for (int j = 0; j < 32; j += 8)
        out[(size_t)(c0 + y + j) * R + r0 + x] = __float2half_rn(t[x][y + j]);
}

// =================== round x -> fp16 ===================
__global__ __launch_bounds__(256)
void round_h(const float* __restrict__ in, __half* __restrict__ out, int n4)
{
    int i = blockIdx.x * 256 + threadIdx.x;
    if (i < n4) {
        float4 v = ((const float4*)in)[i];
        __half2* o = (__half2*)(out + (size_t)i * 4);
        o[0] = __floats2half2_rn(v.x, v.y);
        o[1] = __floats2half2_rn(v.z, v.w);
    }
}

// =================== rinv[r] = 1 / sum over 64 column-block partials ===================
__global__ __launch_bounds__(256)
void reduce_rinv(const float* __restrict__ spart, float* __restrict__ rinv)
{
    const int r = blockIdx.x * 256 + threadIdx.x;
    float s = 0.f;
    #pragma unroll
    for (int cb = 0; cb < 64; cb++)
        s += spart[(size_t)cb * N_TOK + r];
    rinv[r] = 1.0f / s;
}

// =================== out = rinv[r] * (p0+p1+p2+p3) ===================
__global__ __launch_bounds__(256)
void reduce_out(const float* __restrict__ p, const float* __restrict__ rinv,
                float* __restrict__ out)
{
    const size_t i = (size_t)blockIdx.x * 256 + threadIdx.x;   // float4 index
    const size_t stride = (size_t)N_TOK * DIM / 4;
    const float sc = rinv[(i * 4) >> 10];                      // DIM = 1024
    const float4* p0 = (const float4*)p;
    float4 a = p0[i], b = p0[i + stride], c = p0[i + 2 * stride], d = p0[i + 3 * stride];
    float4 o;
    o.x = (a.x + b.x + c.x + d.x) * sc;
    o.y = (a.y + b.y + c.y + d.y) * sc;
    o.z = (a.z + b.z + c.z + d.z) * sc;
    o.w = (a.w + b.w + c.w + d.w) * sc;
    ((float4*)out)[i] = o;
}

// =================== host ===================
extern "C" void kernel_launch(void* const* d_in, const int* in_sizes, int n_in,
                              void* d_out, int out_size)
{
    const float* x  = (const float*)d_in[0];
    const float* Wq = (const float*)d_in[1];
    const float* Wk = (const float*)d_in[2];
    const float* Wv = (const float*)d_in[3];
    float* out = (float*)d_out;

    __half *X, *Q, *K, *VT, *WT, *S;
    float *Spart, *Opart, *Rinv;
    cudaGetSymbolAddress((void**)&X,     g_X);
    cudaGetSymbolAddress((void**)&Q,     g_Q);
    cudaGetSymbolAddress((void**)&K,     g_K);
    cudaGetSymbolAddress((void**)&VT,    g_VT);
    cudaGetSymbolAddress((void**)&WT,    g_WT);
    cudaGetSymbolAddress((void**)&S,     g_S);
    cudaGetSymbolAddress((void**)&Spart, g_spart);
    cudaGetSymbolAddress((void**)&Opart, g_opart);
    cudaGetSymbolAddress((void**)&Rinv,  g_rinv);
    __half* WkT = WT;
    __half* WqT = WT + (size_t)DIM * DIM;
    __half* WvT = WT + (size_t)2 * DIM * DIM;

    cudaFuncSetAttribute(gemm_h<1>, cudaFuncAttributeMaxDynamicSharedMemorySize, SMEM_BYTES);
    cudaFuncSetAttribute(gemm_h<2>, cudaFuncAttributeMaxDynamicSharedMemorySize, SMEM_BYTES);
    cudaFuncSetAttribute(gemm_h<3>, cudaFuncAttributeMaxDynamicSharedMemorySize, SMEM_BYTES);
    cudaFuncSetAttribute(gemm_h<4>, cudaFuncAttributeMaxDynamicSharedMemorySize, SMEM_BYTES);

    const dim3 tblk(32, 8);

    // prep: x -> fp16; W -> fp16 transposed ([in,out] -> [out,in])
    round_h<<<(N_TOK * DIM / 4 + 255) / 256, 256>>>(x, X, N_TOK * DIM / 4);
    transpose_f2h<<<dim3(32, 32), tblk>>>(Wk, WkT, DIM, DIM);
    transpose_f2h<<<dim3(32, 32), tblk>>>(Wq, WqT, DIM, DIM);
    transpose_f2h<<<dim3(32, 32), tblk>>>(Wv, WvT, DIM, DIM);

    const dim3 gProj(DIM / BN, N_TOK / BM);        // (8, 64)
    const dim3 gScore(N_TOK / BN, N_TOK / BM);     // (64, 64)
    const dim3 gPV(DIM / BN, N_TOK / BM, 4);       // (8, 64, 4) split-K

    // reference name-swap: q = x@Wk, k = x@Wq, v = x@Wv
    gemm_h<1><<<gProj, 256, SMEM_BYTES>>>(X, WkT, Q, N_TOK, DIM, DIM, 1.f, nullptr);
    gemm_h<1><<<gProj, 256, SMEM_BYTES>>>(X, WqT, K, N_TOK, DIM, DIM, 1.f, nullptr);
    // V projection writes VT directly (transposed epilogue)
    gemm_h<3><<<gProj, 256, SMEM_BYTES>>>(X, WvT, VT, N_TOK, DIM, DIM, 1.f, nullptr);

    // P = exp(QK^T / 32) fp16 + fused row partial sums
    gemm_h<2><<<gScore, 256, SMEM_BYTES>>>(Q, K, S, N_TOK, N_TOK, DIM, 0.03125f, Spart);
    reduce_rinv<<<N_TOK / 256, 256>>>(Spart, Rinv);

    // PV split-K=4 -> fp32 partials, then reduce+normalize
    gemm_h<4><<<gPV, 256, SMEM_BYTES>>>(S, VT, Opart, N_TOK, DIM, N_TOK, 1.f, nullptr);
    reduce_out<<<(N_TOK * DIM / 4) / 256, 256>>>(Opart, Rinv, out);
}

// round 8
// speedup vs baseline: 1.1951x; 1.0235x over previous
#include <cuda_runtime.h>
#include <cuda_fp16.h>
#include <cstdint>

#define N_TOK 8192
#define DIM   1024

// ---- fp16 mma tile config: CTA 128x128x32, warp 64x32, 8 warps, 2 CTA/SM ----
#define BM 128
#define BN 128
#define BK 32
#define NST 4
#define RSH 40                        // halves per smem row (80 B)
#define OPB (128 * RSH * 2)           // 10240 B per operand per stage
#define SS  (2 * OPB)                 // 20480 B per stage
#define SMEM_BYTES (NST * SS)         // 81920 B

// ---- scratch (device globals; no allocation allowed) ----
__device__ __half g_X [N_TOK * DIM];
__device__ __half g_Q [N_TOK * DIM];
__device__ __half g_K [N_TOK * DIM];
__device__ __half g_VT[N_TOK * DIM];
__device__ __half g_WT[3 * DIM * DIM];                  // [WkT | WqT | WvT]
__device__ __half g_S [(size_t)N_TOK * N_TOK];
__device__ float  g_spart[(size_t)64 * N_TOK];          // score row partial sums
__device__ float  g_opart[(size_t)4 * N_TOK * DIM];     // PV split-K partials
__device__ float  g_rinv[N_TOK];

// =================== helpers ===================
__device__ __forceinline__ uint32_t smem_u32(const void* p) {
    uint32_t a;
    asm("{ .reg .u64 t; cvta.to.shared.u64 t, %1; cvt.u32.u64 %0, t; }" : "=r"(a) : "l"(p));
    return a;
}
__device__ __forceinline__ void cp16(uint32_t dst, const void* src) {
    asm volatile("cp.async.cg.shared.global [%0], [%1], 16;" :: "r"(dst), "l"(src));
}
__device__ __forceinline__ void cp_commit() {
    asm volatile("cp.async.commit_group;" ::: "memory");
}
__device__ __forceinline__ void cp_wait2() {
    asm volatile("cp.async.wait_group 2;" ::: "memory");
}
__device__ __forceinline__ void ldsm4(uint32_t* r, uint32_t addr) {
    asm volatile("ldmatrix.sync.aligned.m8n8.x4.shared.b16 {%0,%1,%2,%3}, [%4];"
                 : "=r"(r[0]), "=r"(r[1]), "=r"(r[2]), "=r"(r[3]) : "r"(addr));
}
__device__ __forceinline__ void mma_f16(float* c, const uint32_t* a, uint32_t b0, uint32_t b1) {
    asm volatile(
        "mma.sync.aligned.m16n8k16.row.col.f32.f16.f16.f32 "
        "{%0,%1,%2,%3}, {%4,%5,%6,%7}, {%8,%9}, {%0,%1,%2,%3};"
        : "+f"(c[0]), "+f"(c[1]), "+f"(c[2]), "+f"(c[3])
        : "r"(a[0]), "r"(a[1]), "r"(a[2]), "r"(a[3]), "r"(b0), "r"(b1));
}

// =================== fp16 mma.sync GEMM ===================
// acc = A[M,K_slice] @ B[N,K_slice]^T  (K sliced by gridDim.z)
// MODE 2: C fp16 = exp(alpha*acc); fused row partial sums -> spart
// MODE 4: partial[z] fp32 = acc                 (PV split-K)
// MODE 5: fused QKV projection. blockIdx.x>>3 selects output:
//         0 -> Q fp16, 1 -> K fp16, 2 -> VT fp16 (smem-transposed epilogue).
//         Cv = Q base; aux1 = K base; aux2 = VT base.
template<int MODE>
__global__ __launch_bounds__(256, 2)
void gemm_h(const __half* __restrict__ A, const __half* __restrict__ B,
            void* __restrict__ Cv, int M, int N, int K,
            float alpha, float* __restrict__ spart,
            __half* __restrict__ aux1, __half* __restrict__ aux2)
{
    extern __shared__ char smraw[];
    const uint32_t sbase = smem_u32(smraw);
    const int tid  = threadIdx.x;
    const int wid  = tid >> 5, lane = tid & 31;
    const int wm   = wid & 1, wn = wid >> 1;
    const int rowBase = blockIdx.y * BM;
    const int colBase = blockIdx.x * BN;          // within B's N (3072 for MODE 5)
    const int kPer = K / gridDim.z;
    const int kOff = blockIdx.z * kPer;
    const int nk = kPer / BK;

    // ---- gmem -> smem: rows of 64B (32 halves); 2 x 16B per operand per thread ----
    const int gr = tid >> 2;                 // 0..63
    const int seg = tid & 3;
    const __half* gA = A + (size_t)(rowBase + gr) * K + kOff + seg * 8;
    const __half* gB = B + (size_t)(colBase + gr) * K + kOff + seg * 8;
    const size_t hop = (size_t)64 * K;
    const uint32_t dA = (uint32_t)gr * 80 + seg * 16;
    const uint32_t dB = OPB + dA;

    // ---- ldmatrix offsets ----
    const int quad = lane >> 3, lr = lane & 7;
    uint32_t aOff[4], bOff[2];
    #pragma unroll
    for (int mt = 0; mt < 4; mt++) {
        int r = wm * 64 + mt * 16 + (quad & 1) * 8 + lr;
        aOff[mt] = (uint32_t)(r * RSH + (quad >> 1) * 8) * 2;
    }
    #pragma unroll
    for (int p = 0; p < 2; p++) {
        int r = wn * 32 + p * 16 + (quad & 1) * 8 + lr;
        bOff[p] = OPB + (uint32_t)(r * RSH + (quad >> 1) * 8) * 2;
    }

    float acc[4][4][4];
    #pragma unroll
    for (int i = 0; i < 4; i++)
        #pragma unroll
        for (int j = 0; j < 4; j++)
            #pragma unroll
            for (int e = 0; e < 4; e++) acc[i][j][e] = 0.f;

    // ---- prologue ----
    #pragma unroll
    for (int s = 0; s < NST - 1; s++) {
        const uint32_t d = sbase + s * SS;
        const int k0 = s * BK;
        cp16(d + dA,           gA + k0);
        cp16(d + dA + 64 * 80, gA + hop + k0);
        cp16(d + dB,           gB + k0);
        cp16(d + dB + 64 * 80, gB + hop + k0);
        cp_commit();
    }

    // ---- main loop ----
    for (int it = 0; it < nk; it++) {
        cp_wait2();
        __syncthreads();

        if (it + NST - 1 < nk) {
            const uint32_t d = sbase + ((it + NST - 1) & (NST - 1)) * SS;
            const int k0 = (it + NST - 1) * BK;
            cp16(d + dA,           gA + k0);
            cp16(d + dA + 64 * 80, gA + hop + k0);
            cp16(d + dB,           gB + k0);
            cp16(d + dB + 64 * 80, gB + hop + k0);
        }
        cp_commit();

        const uint32_t st = sbase + (it & (NST - 1)) * SS;
        #pragma unroll
        for (int kk = 0; kk < 2; kk++) {
            const uint32_t ko = kk * 32;
            uint32_t a[4][4], b[2][4];
            #pragma unroll
            for (int mt = 0; mt < 4; mt++) ldsm4(a[mt], st + aOff[mt] + ko);
            #pragma unroll
            for (int p = 0; p < 2; p++)    ldsm4(b[p],  st + bOff[p] + ko);
            #pragma unroll
            for (int mt = 0; mt < 4; mt++)
                #pragma unroll
                for (int p = 0; p < 2; p++) {
                    mma_f16(acc[mt][2*p],   a[mt], b[p][0], b[p][2]);
                    mma_f16(acc[mt][2*p+1], a[mt], b[p][1], b[p][3]);
                }
        }
        __syncthreads();
    }

    // ---- epilogue ----
    const int g = lane >> 2, tg = lane & 3;

    if (MODE == 2) {
        float rs0[4] = {0.f, 0.f, 0.f, 0.f};
        float rs1[4] = {0.f, 0.f, 0.f, 0.f};
        __half* C = (__half*)Cv;
        #pragma unroll
        for (int mt = 0; mt < 4; mt++) {
            const int r0 = rowBase + wm * 64 + mt * 16 + g;
            #pragma unroll
            for (int nt = 0; nt < 4; nt++) {
                const int c = colBase + wn * 32 + nt * 8 + tg * 2;
                float v0 = __expf(alpha * acc[mt][nt][0]);
                float v1 = __expf(alpha * acc[mt][nt][1]);
                float v2 = __expf(alpha * acc[mt][nt][2]);
                float v3 = __expf(alpha * acc[mt][nt][3]);
                rs0[mt] += v0 + v1;
                rs1[mt] += v2 + v3;
                *(__half2*)&C[(size_t)r0 * N + c]       = __floats2half2_rn(v0, v1);
                *(__half2*)&C[(size_t)(r0 + 8) * N + c] = __floats2half2_rn(v2, v3);
            }
        }
        // reduce row partials across lanes, then across wn warps via smem
        float* part = (float*)smraw;           // [4][128]
        __syncthreads();
        #pragma unroll
        for (int mt = 0; mt < 4; mt++) {
            float a0 = rs0[mt], a1 = rs1[mt];
            a0 += __shfl_xor_sync(0xffffffffu, a0, 1);
            a0 += __shfl_xor_sync(0xffffffffu, a0, 2);
            a1 += __shfl_xor_sync(0xffffffffu, a1, 1);
            a1 += __shfl_xor_sync(0xffffffffu, a1, 2);
            if (tg == 0) {
                part[wn * 128 + wm * 64 + mt * 16 + g]     = a0;
                part[wn * 128 + wm * 64 + mt * 16 + g + 8] = a1;
            }
        }
        __syncthreads();
        if (tid < 128) {
            float s = part[tid] + part[128 + tid] + part[256 + tid] + part[384 + tid];
            spart[(size_t)blockIdx.x * M + rowBase + tid] = s;
        }
    } else if (MODE == 5) {
        const int grp = blockIdx.x >> 3;               // 0=Q, 1=K, 2=VT
        const int colLoc = (blockIdx.x & 7) * BN;      // column within 1024
        if (grp < 2) {
            __half* C = grp == 0 ? (__half*)Cv : aux1;
            #pragma unroll
            for (int mt = 0; mt < 4; mt++) {
                const int r0 = rowBase + wm * 64 + mt * 16 + g;
                #pragma unroll
                for (int nt = 0; nt < 4; nt++) {
                    const int c = colLoc + wn * 32 + nt * 8 + tg * 2;
                    *(__half2*)&C[(size_t)r0 * DIM + c] =
                        __floats2half2_rn(acc[mt][nt][0], acc[mt][nt][1]);
                    *(__half2*)&C[(size_t)(r0 + 8) * DIM + c] =
                        __floats2half2_rn(acc[mt][nt][2], acc[mt][nt][3]);
                }
            }
        } else {
            // transpose tile in smem, write VT coalesced
            __half* buf = (__half*)smraw;              // [128 cols][136 rows]
            __syncthreads();
            #pragma unroll
            for (int mt = 0; mt < 4; mt++) {
                const int r0 = wm * 64 + mt * 16 + g;
                #pragma unroll
                for (int nt = 0; nt < 4; nt++) {
                    const int c = wn * 32 + nt * 8 + tg * 2;
                    buf[(c    ) * 136 + r0    ] = __float2half_rn(acc[mt][nt][0]);
                    buf[(c + 1) * 136 + r0    ] = __float2half_rn(acc[mt][nt][1]);
                    buf[(c    ) * 136 + r0 + 8] = __float2half_rn(acc[mt][nt][2]);
                    buf[(c + 1) * 136 + r0 + 8] = __float2half_rn(acc[mt][nt][3]);
                }
            }
            __syncthreads();
            __half* VT = aux2;                         // [DIM][N_TOK]
            #pragma unroll
            for (int ch = tid; ch < 128 * 16; ch += 256) {
                const int cc = ch >> 4, sg = ch & 15;
                uint4 v = *(uint4*)&buf[cc * 136 + sg * 8];
                *(uint4*)&VT[(size_t)(colLoc + cc) * M + rowBase + sg * 8] = v;
            }
        }
    } else {  // MODE 4: fp32 split-K partial
        float* C = (float*)Cv + (size_t)blockIdx.z * M * N;
        #pragma unroll
        for (int mt = 0; mt < 4; mt++) {
            const int r0 = rowBase + wm * 64 + mt * 16 + g;
            #pragma unroll
            for (int nt = 0; nt < 4; nt++) {
                const int c = colBase + wn * 32 + nt * 8 + tg * 2;
                *(float2*)&C[(size_t)r0 * N + c]       = make_float2(acc[mt][nt][0], acc[mt][nt][1]);
                *(float2*)&C[(size_t)(r0 + 8) * N + c] = make_float2(acc[mt][nt][2], acc[mt][nt][3]);
            }
        }
    }
}

// =================== 3-way weight transpose fp32 -> fp16 ===================
// z selects Wk/Wq/Wv; writes into WT + z*DIM*DIM ([in,out] -> [out,in])
__global__ void transpose3_f2h(const float* __restrict__ w0, const float* __restrict__ w1,
                               const float* __restrict__ w2, __half* __restrict__ out)
{
    __shared__ float t[32][33];
    const float* in = blockIdx.z == 0 ? w0 : (blockIdx.z == 1 ? w1 : w2);
    __half* o = out + (size_t)blockIdx.z * DIM * DIM;
    const int c0 = blockIdx.x * 32, r0 = blockIdx.y * 32;
    const int x = threadIdx.x, y = threadIdx.y;
    #pragma unroll
    for (int j = 0; j < 32; j += 8)
        t[y + j][x] = in[(size_t)(r0 + y + j) * DIM + c0 + x];
    __syncthreads();
    #pragma unroll
    for (int j = 0; j < 32; j += 8)
        o[(size_t)(c0 + y + j) * DIM + r0 + x] = __float2half_rn(t[x][y + j]);
}

// =================== round x -> fp16 ===================
__global__ __launch_bounds__(256)
void round_h(const float* __restrict__ in, __half* __restrict__ out, int n4)
{
    int i = blockIdx.x * 256 + threadIdx.x;
    if (i < n4) {
        float4 v = ((const float4*)in)[i];
        __half2* o = (__half2*)(out + (size_t)i * 4);
        o[0] = __floats2half2_rn(v.x, v.y);
        o[1] = __floats2half2_rn(v.z, v.w);
    }
}

// =================== rinv[r] = 1 / sum over 64 column-block partials ===================
__global__ __launch_bounds__(256)
void reduce_rinv(const float* __restrict__ spart, float* __restrict__ rinv)
{
    const int r = blockIdx.x * 256 + threadIdx.x;
    float s = 0.f;
    #pragma unroll
    for (int cb = 0; cb < 64; cb++)
        s += spart[(size_t)cb * N_TOK + r];
    rinv[r] = 1.0f / s;
}

// =================== out = rinv[r] * (p0+p1+p2+p3) ===================
__global__ __launch_bounds__(256)
void reduce_out(const float* __restrict__ p, const float* __restrict__ rinv,
                float* __restrict__ out)
{
    const size_t i = (size_t)blockIdx.x * 256 + threadIdx.x;   // float4 index
    const size_t stride = (size_t)N_TOK * DIM / 4;
    const float sc = rinv[(i * 4) >> 10];                      // DIM = 1024
    const float4* p0 = (const float4*)p;
    float4 a = p0[i], b = p0[i + stride], c = p0[i + 2 * stride], d = p0[i + 3 * stride];
    float4 o;
    o.x = (a.x + b.x + c.x + d.x) * sc;
    o.y = (a.y + b.y + c.y + d.y) * sc;
    o.z = (a.z + b.z + c.z + d.z) * sc;
    o.w = (a.w + b.w + c.w + d.w) * sc;
    ((float4*)out)[i] = o;
}

// =================== host ===================
extern "C" void kernel_launch(void* const* d_in, const int* in_sizes, int n_in,
                              void* d_out, int out_size)
{
    const float* x  = (const float*)d_in[0];
    const float* Wq = (const float*)d_in[1];
    const float* Wk = (const float*)d_in[2];
    const float* Wv = (const float*)d_in[3];
    float* out = (float*)d_out;

    __half *X, *Q, *K, *VT, *WT, *S;
    float *Spart, *Opart, *Rinv;
    cudaGetSymbolAddress((void**)&X,     g_X);
    cudaGetSymbolAddress((void**)&Q,     g_Q);
    cudaGetSymbolAddress((void**)&K,     g_K);
    cudaGetSymbolAddress((void**)&VT,    g_VT);
    cudaGetSymbolAddress((void**)&WT,    g_WT);
    cudaGetSymbolAddress((void**)&S,     g_S);
    cudaGetSymbolAddress((void**)&Spart, g_spart);
    cudaGetSymbolAddress((void**)&Opart, g_opart);
    cudaGetSymbolAddress((void**)&Rinv,  g_rinv);

    cudaFuncSetAttribute(gemm_h<2>, cudaFuncAttributeMaxDynamicSharedMemorySize, SMEM_BYTES);
    cudaFuncSetAttribute(gemm_h<4>, cudaFuncAttributeMaxDynamicSharedMemorySize, SMEM_BYTES);
    cudaFuncSetAttribute(gemm_h<5>, cudaFuncAttributeMaxDynamicSharedMemorySize, SMEM_BYTES);

    // prep: x -> fp16; W -> fp16 transposed, packed [WkT|WqT|WvT]
    round_h<<<(N_TOK * DIM / 4 + 255) / 256, 256>>>(x, X, N_TOK * DIM / 4);
    transpose3_f2h<<<dim3(32, 32, 3), dim3(32, 8)>>>(Wk, Wq, Wv, WT);

    // fused QKV projection (reference name-swap: q = x@Wk, k = x@Wq, v = x@Wv)
    const dim3 gQKV(3 * DIM / BN, N_TOK / BM);     // (24, 64)
    gemm_h<5><<<gQKV, 256, SMEM_BYTES>>>(X, WT, Q, N_TOK, 3 * DIM, DIM, 1.f, nullptr, K, VT);

    // P = exp(QK^T / 32) fp16 + fused row partial sums
    const dim3 gScore(N_TOK / BN, N_TOK / BM);     // (64, 64)
    gemm_h<2><<<gScore, 256, SMEM_BYTES>>>(Q, K, S, N_TOK, N_TOK, DIM, 0.03125f, Spart, nullptr, nullptr);
    reduce_rinv<<<N_TOK / 256, 256>>>(Spart, Rinv);

    // PV split-K=4 -> fp32 partials, then reduce+normalize
    const dim3 gPV(DIM / BN, N_TOK / BM, 4);       // (8, 64, 4)
    gemm_h<4><<<gPV, 256, SMEM_BYTES>>>(S, VT, Opart, N_TOK, DIM, N_TOK, 1.f, nullptr, nullptr, nullptr);
    reduce_out<<<(N_TOK * DIM / 4) / 256, 256>>>(Opart, Rinv, out);
}